// round 1
// baseline (speedup 1.0000x reference)
#include <cuda_runtime.h>
#include <cstdint>
#include <cstddef>

// ---------------------------------------------------------------------------
// Fused "sigmoid attention" pipeline:
//   q = Wq x + bq ; k = Wk x + bk ; vT = xT Wv^T + bv
//   alpha = sigmoid(q^T k)  (materialized, 268MB scratch)
//   out   = vT^T-contracted: out[c,m] = sum_n vT[n,c] * alpha[n,m]
// All GEMMs in TN form: C[M,N] = sum_k A[k,m] * B[k,n], A:[K,M], B:[K,N] row-major.
// TF32 mma.sync m16n8k8, operands pre-rounded to TF32 (RN) for precision.
// ---------------------------------------------------------------------------

#define BM 128
#define BN 128
#define BK 32
#define LDT 132               // BM + 4 float pad (conflict-free fragment loads)
#define SMEM_BYTES (2 * 2 * BK * LDT * 4)   // 2 ops (A,B) x 2 buffers = 67584 B

// ------------------------------- scratch -----------------------------------
static __device__ float g_xr  [(size_t)4 * 512 * 4096];   // x rounded to tf32
static __device__ float g_Wqt [512 * 1024];               // Wq^T, padded 1000->1024 w/ zeros
static __device__ float g_bqp [1024];
static __device__ float g_Wkt [512 * 1024];
static __device__ float g_bkp [1024];
static __device__ float g_Wvt [512 * 512];                // Wv^T
static __device__ float g_bvp [512];
static __device__ float g_q   [(size_t)4 * 1024 * 4096];  // q[b][o][n]
static __device__ float g_k2  [(size_t)4 * 1024 * 4096];  // k[b][o][n]
static __device__ float g_vT  [(size_t)4 * 4096 * 512];   // vT[b][n][c]
static __device__ float g_alp [(size_t)4 * 4096 * 4096];  // alpha[b][n][m]

// ------------------------------ helpers ------------------------------------
__device__ __forceinline__ float rn_tf32(float x) {
    uint32_t u;
    asm("cvt.rna.tf32.f32 %0, %1;" : "=r"(u) : "f"(x));
    return __uint_as_float(u);
}

__device__ __forceinline__ void mma_tf32(float* d, const uint32_t* a, const uint32_t* b) {
    asm volatile(
        "mma.sync.aligned.m16n8k8.row.col.f32.tf32.tf32.f32 "
        "{%0,%1,%2,%3}, {%4,%5,%6,%7}, {%8,%9}, {%0,%1,%2,%3};\n"
        : "+f"(d[0]), "+f"(d[1]), "+f"(d[2]), "+f"(d[3])
        : "r"(a[0]), "r"(a[1]), "r"(a[2]), "r"(a[3]), "r"(b[0]), "r"(b[1]));
}

// ---------------------------- prep kernels ----------------------------------
__global__ void round_copy(const float* __restrict__ in, float* __restrict__ out, size_t n) {
    size_t i = (size_t)blockIdx.x * blockDim.x + threadIdx.x;
    size_t stride = (size_t)gridDim.x * blockDim.x;
    for (; i < n; i += stride) out[i] = rn_tf32(in[i]);
}

// Wt[k][m] = (m < Mvalid) ? rn(W[m][k]) : 0 ; bp[m] = (m < Mvalid) ? b[m] : 0
__global__ void transpose_pad(const float* __restrict__ W, const float* __restrict__ b,
                              float* __restrict__ Wt, float* __restrict__ bp,
                              int Mout, int Mvalid, int Kd) {
    int idx = blockIdx.x * blockDim.x + threadIdx.x;
    int total = Kd * Mout;
    if (idx < total) {
        int k = idx / Mout;
        int m = idx - k * Mout;
        Wt[idx] = (m < Mvalid) ? rn_tf32(W[(size_t)m * Kd + k]) : 0.0f;
    }
    if (idx < Mout) bp[idx] = (idx < Mvalid) ? b[idx] : 0.0f;
}

// ------------------------------ GEMM (TN) -----------------------------------
// EPI: 0 = plain store
//      1 = +bias[row m], round tf32
//      2 = +bias[col n], round tf32
//      3 = sigmoid, round tf32
template <int EPI>
__global__ __launch_bounds__(256, 2)
void gemm_tn(const float* __restrict__ Ag, const float* __restrict__ Bg,
             float* __restrict__ Cg, const float* __restrict__ bias,
             int M, int N, int K, size_t sA, size_t sB, size_t sC) {
    extern __shared__ float smem[];
    float* As = smem;                          // [2][BK][LDT]
    float* Bs = smem + 2 * BK * LDT;           // [2][BK][LDT]

    const float* A = Ag + (size_t)blockIdx.z * sA;
    const float* B = Bg + (size_t)blockIdx.z * sB;
    float*       C = Cg + (size_t)blockIdx.z * sC;

    const int m0 = blockIdx.y * BM;
    const int n0 = blockIdx.x * BN;
    const int tid  = threadIdx.x;
    const int w    = tid >> 5;
    const int lane = tid & 31;
    const int g    = lane >> 2;        // groupID
    const int tg   = lane & 3;         // threadID_in_group
    const int wm   = (w & 1) * 64;     // warp m offset (2 warps over M)
    const int wn   = (w >> 1) * 32;    // warp n offset (4 warps over N)

    const unsigned sA0 = (unsigned)__cvta_generic_to_shared(As);
    const unsigned sB0 = (unsigned)__cvta_generic_to_shared(Bs);

    const int kt = K / BK;

    auto issue = [&](int t, int buf) {
        const float* Ab = A + (size_t)t * BK * M + m0;
        const float* Bb = B + (size_t)t * BK * N + n0;
        const unsigned abase = sA0 + (unsigned)(buf * BK * LDT * 4);
        const unsigned bbase = sB0 + (unsigned)(buf * BK * LDT * 4);
#pragma unroll
        for (int i = 0; i < 4; i++) {
            int idx = tid + i * 256;          // 0..1023 = 32 k-rows x 32 float4
            int k  = idx >> 5;
            int m4 = (idx & 31) << 2;
            asm volatile("cp.async.cg.shared.global [%0], [%1], 16;\n" ::
                "r"(abase + (unsigned)((k * LDT + m4) * 4)),
                "l"(Ab + (size_t)k * M + m4) : "memory");
            asm volatile("cp.async.cg.shared.global [%0], [%1], 16;\n" ::
                "r"(bbase + (unsigned)((k * LDT + m4) * 4)),
                "l"(Bb + (size_t)k * N + m4) : "memory");
        }
        asm volatile("cp.async.commit_group;\n" ::: "memory");
    };

    float acc[4][4][4];
#pragma unroll
    for (int i = 0; i < 4; i++)
#pragma unroll
        for (int j = 0; j < 4; j++)
#pragma unroll
            for (int r = 0; r < 4; r++) acc[i][j][r] = 0.0f;

    issue(0, 0);
    int buf = 0;
    for (int t = 0; t < kt; t++) {
        asm volatile("cp.async.wait_group 0;\n" ::: "memory");
        __syncthreads();
        if (t + 1 < kt) issue(t + 1, buf ^ 1);

        const float* Asb = As + buf * BK * LDT;
        const float* Bsb = Bs + buf * BK * LDT;
#pragma unroll
        for (int ks = 0; ks < 4; ks++) {
            const int k8 = ks * 8;
            uint32_t af[4][4], bf[4][2];
#pragma unroll
            for (int im = 0; im < 4; im++) {
                const int r = wm + im * 16 + g;
                // tf32 m16n8k8 A frag: a0=(g,tg) a1=(g+8,tg) a2=(g,tg+4) a3=(g+8,tg+4)
                af[im][0] = __float_as_uint(Asb[(k8 + tg)     * LDT + r]);
                af[im][1] = __float_as_uint(Asb[(k8 + tg)     * LDT + r + 8]);
                af[im][2] = __float_as_uint(Asb[(k8 + tg + 4) * LDT + r]);
                af[im][3] = __float_as_uint(Asb[(k8 + tg + 4) * LDT + r + 8]);
            }
#pragma unroll
            for (int in = 0; in < 4; in++) {
                const int c = wn + in * 8 + g;
                // B frag: b0=(tg, g) b1=(tg+4, g)
                bf[in][0] = __float_as_uint(Bsb[(k8 + tg)     * LDT + c]);
                bf[in][1] = __float_as_uint(Bsb[(k8 + tg + 4) * LDT + c]);
            }
#pragma unroll
            for (int im = 0; im < 4; im++)
#pragma unroll
                for (int in = 0; in < 4; in++)
                    mma_tf32(acc[im][in], af[im], bf[in]);
        }
        buf ^= 1;
    }

    // epilogue: C frag c0=(g,2tg) c1=(g,2tg+1) c2=(g+8,2tg) c3=(g+8,2tg+1)
#pragma unroll
    for (int im = 0; im < 4; im++) {
        const int r0 = m0 + wm + im * 16 + g;
#pragma unroll
        for (int in = 0; in < 4; in++) {
            const int c = n0 + wn + in * 8 + 2 * tg;
#pragma unroll
            for (int h = 0; h < 2; h++) {
                const int r = r0 + h * 8;
                float vx = acc[im][in][2 * h];
                float vy = acc[im][in][2 * h + 1];
                if (EPI == 1) { float bb = bias[r]; vx += bb; vy += bb; }
                if (EPI == 2) { vx += bias[c]; vy += bias[c + 1]; }
                if (EPI == 3) {
                    vx = 1.0f / (1.0f + __expf(-vx));
                    vy = 1.0f / (1.0f + __expf(-vy));
                }
                if (EPI != 0) { vx = rn_tf32(vx); vy = rn_tf32(vy); }
                float2 v2 = make_float2(vx, vy);
                *reinterpret_cast<float2*>(&C[(size_t)r * N + c]) = v2;
            }
        }
    }
}

// ------------------------------- launch -------------------------------------
extern "C" void kernel_launch(void* const* d_in, const int* in_sizes, int n_in,
                              void* d_out, int out_size) {
    (void)in_sizes; (void)n_in; (void)out_size;
    const float* x  = (const float*)d_in[0];
    const float* Wq = (const float*)d_in[1];
    const float* bq = (const float*)d_in[2];
    const float* Wk = (const float*)d_in[3];
    const float* bk = (const float*)d_in[4];
    const float* Wv = (const float*)d_in[5];
    const float* bv = (const float*)d_in[6];
    float* out = (float*)d_out;

    float *xr, *Wqt, *bqp, *Wkt, *bkp, *Wvt, *bvp, *q, *k, *vT, *alpha;
    cudaGetSymbolAddress((void**)&xr,  g_xr);
    cudaGetSymbolAddress((void**)&Wqt, g_Wqt);
    cudaGetSymbolAddress((void**)&bqp, g_bqp);
    cudaGetSymbolAddress((void**)&Wkt, g_Wkt);
    cudaGetSymbolAddress((void**)&bkp, g_bkp);
    cudaGetSymbolAddress((void**)&Wvt, g_Wvt);
    cudaGetSymbolAddress((void**)&bvp, g_bvp);
    cudaGetSymbolAddress((void**)&q,   g_q);
    cudaGetSymbolAddress((void**)&k,   g_k2);
    cudaGetSymbolAddress((void**)&vT,  g_vT);
    cudaGetSymbolAddress((void**)&alpha, g_alp);

    cudaFuncSetAttribute(gemm_tn<0>, cudaFuncAttributeMaxDynamicSharedMemorySize, SMEM_BYTES);
    cudaFuncSetAttribute(gemm_tn<1>, cudaFuncAttributeMaxDynamicSharedMemorySize, SMEM_BYTES);
    cudaFuncSetAttribute(gemm_tn<2>, cudaFuncAttributeMaxDynamicSharedMemorySize, SMEM_BYTES);
    cudaFuncSetAttribute(gemm_tn<3>, cudaFuncAttributeMaxDynamicSharedMemorySize, SMEM_BYTES);

    const size_t nX = (size_t)4 * 512 * 4096;
    round_copy<<<2048, 256>>>(x, xr, nX);
    transpose_pad<<<(512 * 1024 + 255) / 256, 256>>>(Wq, bq, Wqt, bqp, 1024, 1000, 512);
    transpose_pad<<<(512 * 1024 + 255) / 256, 256>>>(Wk, bk, Wkt, bkp, 1024, 1000, 512);
    transpose_pad<<<(512 * 512  + 255) / 256, 256>>>(Wv, bv, Wvt, bvp,  512,  512, 512);

    dim3 blk(256);
    const size_t sX = (size_t)512 * 4096;     // per-batch x
    const size_t sQ = (size_t)1024 * 4096;    // per-batch q/k
    const size_t sV = (size_t)4096 * 512;     // per-batch vT
    const size_t sS = (size_t)4096 * 4096;    // per-batch alpha
    const size_t sO = (size_t)512 * 4096;     // per-batch out

    // q[b][o][n] = Wq x + bq   (M=1024 padded, N=4096, K=512)
    gemm_tn<1><<<dim3(32, 8, 4), blk, SMEM_BYTES>>>(Wqt, xr, q, bqp, 1024, 4096, 512, 0, sX, sQ);
    // k[b][o][n]
    gemm_tn<1><<<dim3(32, 8, 4), blk, SMEM_BYTES>>>(Wkt, xr, k, bkp, 1024, 4096, 512, 0, sX, sQ);
    // vT[b][n][c] = x^T Wv^T + bv  (M=4096, N=512, K=512), bias per column c
    gemm_tn<2><<<dim3(4, 32, 4), blk, SMEM_BYTES>>>(xr, Wvt, vT, bvp, 4096, 512, 512, sX, 0, sV);
    // alpha[b][n][m] = sigmoid(sum_o q[o][n] k[o][m])  (M=N=4096, K=1024)
    gemm_tn<3><<<dim3(32, 32, 4), blk, SMEM_BYTES>>>(q, k, alpha, nullptr, 4096, 4096, 1024, sQ, sQ, sS);
    // out[b][c][m] = sum_n vT[n][c] alpha[n][m]  (M=512, N=4096, K=4096)
    gemm_tn<0><<<dim3(32, 4, 4), blk, SMEM_BYTES>>>(vT, alpha, out, nullptr, 512, 4096, 4096, sV, sS, sO);
}

// round 3
// speedup vs baseline: 2.6314x; 2.6314x over previous
#include <cuda_runtime.h>
#include <cuda_fp16.h>
#include <cstdint>
#include <cstddef>

// ---------------------------------------------------------------------------
// Sigmoid attention via 5 fp16 mma.sync.m16n8k16 GEMMs (legacy HMMA path;
// tcgen05 is unavailable: harness compiles through virtual arch compute_100).
//   qT[n,o]  = xT[n,c]*Wq[o,c] + bq[o]
//   kT[m,o]  = xT[m,c]*Wk[o,c] + bk[o]
//   v[c,n]   = Wv[c,c']*xT[n,c'] + bv[c]
//   aT[m,n]  = sigmoid(kT[m,o]*qT[n,o])
//   out[c,m] = v[c,n]*aT[m,n]
// All GEMMs: D[m,n] = sum_k A[m,k]*B[n,k], A/B K-contiguous fp16, fp32 accum.
// ldmatrix.x4 fragment loads from xor-swizzled smem; 3-stage cp.async pipe.
// ---------------------------------------------------------------------------

#define BM 128
#define BN 128
#define BKH 64                    // K halves per chunk (128 B per row)
#define STAGE 32768               // A tile 16KB + B tile 16KB
#define NSTAGE 3
#define SMEM_TOTAL (NSTAGE * STAGE)

// ------------------------------- scratch ------------------------------------
#define AL16 __align__(16)
static __device__ AL16 __half g_xT [(size_t)4*4096*512];    // xT[b][n][c]
static __device__ AL16 __half g_Wq [1024*512];              // padded rows 1000->1024
static __device__ AL16 __half g_Wk [1024*512];
static __device__ AL16 __half g_Wv [512*512];
static __device__ float g_bq[1024], g_bk[1024], g_bv[512];
static __device__ AL16 __half g_q  [(size_t)4*4096*1024];   // qT[b][n][o]
static __device__ AL16 __half g_k  [(size_t)4*4096*1024];   // kT[b][m][o]
static __device__ AL16 __half g_v  [(size_t)4*512*4096];    // v[b][c][n]
static __device__ AL16 __half g_a  [(size_t)4*4096*4096];   // aT[b][m][n]

// ------------------------------- helpers ------------------------------------
__device__ __forceinline__ void ldsm_x4(uint32_t& r0, uint32_t& r1, uint32_t& r2, uint32_t& r3,
                                        uint32_t addr) {
    asm volatile("ldmatrix.sync.aligned.m8n8.x4.shared.b16 {%0,%1,%2,%3}, [%4];"
                 : "=r"(r0), "=r"(r1), "=r"(r2), "=r"(r3) : "r"(addr));
}

__device__ __forceinline__ void mma_fp16(float* d, const uint32_t* a, const uint32_t* b) {
    asm volatile(
        "mma.sync.aligned.m16n8k16.row.col.f32.f16.f16.f32 "
        "{%0,%1,%2,%3}, {%4,%5,%6,%7}, {%8,%9}, {%0,%1,%2,%3};\n"
        : "+f"(d[0]), "+f"(d[1]), "+f"(d[2]), "+f"(d[3])
        : "r"(a[0]), "r"(a[1]), "r"(a[2]), "r"(a[3]), "r"(b[0]), "r"(b[1]));
}

// ---------------------------- prep kernels ----------------------------------
// x[b][c][n] fp32 -> xT[b][n][c] fp16
__global__ void xpose_h(const float* __restrict__ x, __half* __restrict__ xT) {
    __shared__ float t[32][33];
    const int b = blockIdx.z;
    const float* xb = x + (size_t)b * 512 * 4096;
    const int n0 = blockIdx.x * 32, c0 = blockIdx.y * 32;
    const int tx = threadIdx.x, ty0 = threadIdx.y;
#pragma unroll
    for (int i = 0; i < 4; i++) {
        int ty = ty0 + i * 8;
        t[ty][tx] = xb[(size_t)(c0 + ty) * 4096 + n0 + tx];
    }
    __syncthreads();
    const size_t ob = (size_t)b * 4096 * 512;
#pragma unroll
    for (int i = 0; i < 4; i++) {
        int ty = ty0 + i * 8;
        xT[ob + (size_t)(n0 + ty) * 512 + c0 + tx] = __float2half_rn(t[tx][ty]);
    }
}

// W[Mvalid][K] fp32 -> fp16 [Mout][K] zero-padded; bias padded
__global__ void conv_pad_w(const float* __restrict__ W, const float* __restrict__ b,
                           __half* __restrict__ Wh, float* __restrict__ bp,
                           int Mout, int Mvalid, int Kd) {
    int idx = blockIdx.x * blockDim.x + threadIdx.x;
    if (idx < Mout * Kd) {
        int m = idx / Kd;
        Wh[idx] = __float2half_rn((m < Mvalid) ? W[idx] : 0.0f);
    }
    if (idx < Mout) bp[idx] = (idx < Mvalid) ? b[idx] : 0.0f;
}

// ------------------------------- GEMM ---------------------------------------
// EPI: 0 = fp32 store ; 1 = +bias[col] -> fp16 ; 2 = +bias[row] -> fp16 ; 3 = sigmoid -> fp16
template <int EPI>
__global__ __launch_bounds__(256, 2)
void gemm_h(const __half* __restrict__ Ag, size_t sA,
            const __half* __restrict__ Bg, size_t sB,
            void* Dg, size_t sD,
            const float* __restrict__ bias,
            int Ntot, int K) {
    extern __shared__ __align__(1024) char smem[];
    const uint32_t sb = (uint32_t)__cvta_generic_to_shared(smem);

    const __half* A = Ag + (size_t)blockIdx.z * sA;
    const __half* B = Bg + (size_t)blockIdx.z * sB;
    const int m0 = blockIdx.y * BM;
    const int n0 = blockIdx.x * BN;
    const int tid  = threadIdx.x;
    const int lane = tid & 31;
    const int w    = tid >> 5;
    const int wm   = (w & 1) * 64;          // 2 warps over M
    const int wn   = (w >> 1) * 32;         // 4 warps over N
    const int g    = lane >> 2;
    const int tg   = lane & 3;

    const int T = K / BKH;

    auto load_stage = [&](int t, int s) {
        const uint32_t st = sb + (uint32_t)(s * STAGE);
        const int kc = t * BKH;
#pragma unroll
        for (int i = 0; i < 8; i++) {
            int idx = tid + i * 256;            // 0..2047
            int isB = idx >> 10;                // first 1024 A, then B
            int r   = (idx & 1023) >> 3;        // row 0..127
            int c   = idx & 7;                  // 16B chunk
            uint32_t dst = st + (uint32_t)(isB * 16384 + r * 128 + ((c ^ (r & 7)) << 4));
            const __half* gp = (isB ? B + (size_t)(n0 + r) * K
                                    : A + (size_t)(m0 + r) * K) + kc + c * 8;
            asm volatile("cp.async.cg.shared.global [%0], [%1], 16;" :: "r"(dst), "l"(gp) : "memory");
        }
        asm volatile("cp.async.commit_group;" ::: "memory");
    };

    float acc[4][4][4];
#pragma unroll
    for (int i = 0; i < 4; i++)
#pragma unroll
        for (int j = 0; j < 4; j++)
#pragma unroll
            for (int r = 0; r < 4; r++) acc[i][j][r] = 0.0f;

    load_stage(0, 0);
    load_stage(1, 1);

    // precomputed ldmatrix lane addressing
    const int rowA = wm + (lane & 15);           // + im*16
    const int hiA  = lane >> 4;                  // chunk +0/+1
    const int rowB = wn + ((lane >> 4) << 3) + (lane & 7);   // + jn*16
    const int hiB  = (lane >> 3) & 1;

    for (int t = 0; t < T; t++) {
        asm volatile("cp.async.wait_group 1;" ::: "memory");
        __syncthreads();
        if (t + 2 < T) load_stage(t + 2, (t + 2) % NSTAGE);

        const uint32_t st  = sb + (uint32_t)((t % NSTAGE) * STAGE);
        const uint32_t stB = st + 16384;
#pragma unroll
        for (int ks = 0; ks < 4; ks++) {
            uint32_t af[4][4], bf[4][2];
#pragma unroll
            for (int im = 0; im < 4; im++) {
                const int r = rowA + im * 16;
                const int c = (ks * 2 + hiA) ^ (r & 7);
                ldsm_x4(af[im][0], af[im][1], af[im][2], af[im][3],
                        st + (uint32_t)(r * 128 + (c << 4)));
            }
#pragma unroll
            for (int jn = 0; jn < 2; jn++) {
                const int r = rowB + jn * 16;
                const int c = (ks * 2 + hiB) ^ (r & 7);
                ldsm_x4(bf[2*jn][0], bf[2*jn][1], bf[2*jn+1][0], bf[2*jn+1][1],
                        stB + (uint32_t)(r * 128 + (c << 4)));
            }
#pragma unroll
            for (int im = 0; im < 4; im++)
#pragma unroll
                for (int in = 0; in < 4; in++)
                    mma_fp16(acc[im][in], af[im], bf[in]);
        }
    }

    // ------------------------------ epilogue ---------------------------------
#pragma unroll
    for (int im = 0; im < 4; im++) {
        const int r0 = m0 + wm + im * 16 + g;
#pragma unroll
        for (int in = 0; in < 4; in++) {
            const int c = n0 + wn + in * 8 + 2 * tg;
#pragma unroll
            for (int h = 0; h < 2; h++) {
                const int r = r0 + h * 8;
                float vx = acc[im][in][2 * h];
                float vy = acc[im][in][2 * h + 1];
                if (EPI == 1) { vx += bias[c]; vy += bias[c + 1]; }
                if (EPI == 2) { float bb = bias[r]; vx += bb; vy += bb; }
                if (EPI == 3) {
                    vx = 1.0f / (1.0f + __expf(-vx));
                    vy = 1.0f / (1.0f + __expf(-vy));
                }
                if (EPI == 0) {
                    float* D = (float*)Dg + (size_t)blockIdx.z * sD + (size_t)r * Ntot + c;
                    *reinterpret_cast<float2*>(D) = make_float2(vx, vy);
                } else {
                    __half* D = (__half*)Dg + (size_t)blockIdx.z * sD + (size_t)r * Ntot + c;
                    *reinterpret_cast<__half2*>(D) = __floats2half2_rn(vx, vy);
                }
            }
        }
    }
}

// ------------------------------- launch -------------------------------------
extern "C" void kernel_launch(void* const* d_in, const int* in_sizes, int n_in,
                              void* d_out, int out_size) {
    (void)in_sizes; (void)n_in; (void)out_size;
    const float* x  = (const float*)d_in[0];
    const float* Wq = (const float*)d_in[1];
    const float* bq = (const float*)d_in[2];
    const float* Wk = (const float*)d_in[3];
    const float* bk = (const float*)d_in[4];
    const float* Wv = (const float*)d_in[5];
    const float* bv = (const float*)d_in[6];
    float* out = (float*)d_out;

    __half *xT,*Wqh,*Wkh,*Wvh,*q,*k,*v,*a;
    float *bqp,*bkp,*bvp;
    cudaGetSymbolAddress((void**)&xT,  g_xT);
    cudaGetSymbolAddress((void**)&Wqh, g_Wq);
    cudaGetSymbolAddress((void**)&Wkh, g_Wk);
    cudaGetSymbolAddress((void**)&Wvh, g_Wv);
    cudaGetSymbolAddress((void**)&bqp, g_bq);
    cudaGetSymbolAddress((void**)&bkp, g_bk);
    cudaGetSymbolAddress((void**)&bvp, g_bv);
    cudaGetSymbolAddress((void**)&q,   g_q);
    cudaGetSymbolAddress((void**)&k,   g_k);
    cudaGetSymbolAddress((void**)&v,   g_v);
    cudaGetSymbolAddress((void**)&a,   g_a);

    cudaFuncSetAttribute(gemm_h<0>, cudaFuncAttributeMaxDynamicSharedMemorySize, SMEM_TOTAL);
    cudaFuncSetAttribute(gemm_h<1>, cudaFuncAttributeMaxDynamicSharedMemorySize, SMEM_TOTAL);
    cudaFuncSetAttribute(gemm_h<2>, cudaFuncAttributeMaxDynamicSharedMemorySize, SMEM_TOTAL);
    cudaFuncSetAttribute(gemm_h<3>, cudaFuncAttributeMaxDynamicSharedMemorySize, SMEM_TOTAL);

    xpose_h<<<dim3(128, 16, 4), dim3(32, 8)>>>(x, xT);
    conv_pad_w<<<(1024*512 + 255)/256, 256>>>(Wq, bq, Wqh, bqp, 1024, 1000, 512);
    conv_pad_w<<<(1024*512 + 255)/256, 256>>>(Wk, bk, Wkh, bkp, 1024, 1000, 512);
    conv_pad_w<<<(512*512  + 255)/256, 256>>>(Wv, bv, Wvh, bvp,  512,  512, 512);

    const size_t sXT = (size_t)4096 * 512;
    const size_t sQT = (size_t)4096 * 1024;
    const size_t sV  = (size_t)512 * 4096;
    const size_t sAL = (size_t)4096 * 4096;
    const size_t sO  = (size_t)512 * 4096;

    // qT[n,o] = xT·Wq (M=4096,N=1024,K=512) + col bias
    gemm_h<1><<<dim3(8, 32, 4), 256, SMEM_TOTAL>>>(xT, sXT, Wqh, 0, q, sQT, bqp, 1024, 512);
    // kT[m,o] = xT·Wk
    gemm_h<1><<<dim3(8, 32, 4), 256, SMEM_TOTAL>>>(xT, sXT, Wkh, 0, k, sQT, bkp, 1024, 512);
    // v[c,n] = Wv·xT (M=512,N=4096,K=512) + row bias
    gemm_h<2><<<dim3(32, 4, 4), 256, SMEM_TOTAL>>>(Wvh, 0, xT, sXT, v, sV, bvp, 4096, 512);
    // aT[m,n] = sigmoid(kT·qT) (M=N=4096,K=1024)
    gemm_h<3><<<dim3(32, 32, 4), 256, SMEM_TOTAL>>>(k, sQT, q, sQT, a, sAL, nullptr, 4096, 1024);
    // out[c,m] = v·aT (M=512,N=4096,K=4096) fp32
    gemm_h<0><<<dim3(32, 4, 4), 256, SMEM_TOTAL>>>(v, sV, a, sAL, out, sO, nullptr, 4096, 4096);
}

// round 4
// speedup vs baseline: 2.9854x; 1.1345x over previous
#include <cuda_runtime.h>
#include <cuda_fp16.h>
#include <cstdint>
#include <cstddef>

// ---------------------------------------------------------------------------
// Sigmoid attention via 5 fp16 mma.sync.m16n8k16 GEMMs (legacy HMMA path;
// tcgen05 unavailable: harness compiles through virtual arch compute_100).
// R4: 64x64 warp tiles (4 warps / 128-thread CTA, 2 CTA/SM), approx-div sigmoid.
//   qT[n,o]  = xT[n,c]*Wq[o,c] + bq[o]
//   kT[m,o]  = xT[m,c]*Wk[o,c] + bk[o]
//   v[c,n]   = Wv[c,c']*xT[n,c'] + bv[c]
//   aT[m,n]  = sigmoid(kT[m,o]*qT[n,o])
//   out[c,m] = v[c,n]*aT[m,n]
// All GEMMs: D[m,n] = sum_k A[m,k]*B[n,k], A/B K-contiguous fp16, fp32 accum.
// ---------------------------------------------------------------------------

#define BM 128
#define BN 128
#define BKH 64                    // K halves per chunk (128 B per row)
#define STAGE 32768               // A tile 16KB + B tile 16KB
#define NSTAGE 3
#define SMEM_TOTAL (NSTAGE * STAGE)

// ------------------------------- scratch ------------------------------------
#define AL16 __align__(16)
static __device__ AL16 __half g_xT [(size_t)4*4096*512];    // xT[b][n][c]
static __device__ AL16 __half g_Wq [1024*512];              // rows padded 1000->1024
static __device__ AL16 __half g_Wk [1024*512];
static __device__ AL16 __half g_Wv [512*512];
static __device__ float g_bq[1024], g_bk[1024], g_bv[512];
static __device__ AL16 __half g_q  [(size_t)4*4096*1024];   // qT[b][n][o]
static __device__ AL16 __half g_k  [(size_t)4*4096*1024];   // kT[b][m][o]
static __device__ AL16 __half g_v  [(size_t)4*512*4096];    // v[b][c][n]
static __device__ AL16 __half g_a  [(size_t)4*4096*4096];   // aT[b][m][n]

// ------------------------------- helpers ------------------------------------
__device__ __forceinline__ void ldsm_x4(uint32_t& r0, uint32_t& r1, uint32_t& r2, uint32_t& r3,
                                        uint32_t addr) {
    asm volatile("ldmatrix.sync.aligned.m8n8.x4.shared.b16 {%0,%1,%2,%3}, [%4];"
                 : "=r"(r0), "=r"(r1), "=r"(r2), "=r"(r3) : "r"(addr));
}

__device__ __forceinline__ void mma_fp16(float* d, const uint32_t* a, const uint32_t* b) {
    asm volatile(
        "mma.sync.aligned.m16n8k16.row.col.f32.f16.f16.f32 "
        "{%0,%1,%2,%3}, {%4,%5,%6,%7}, {%8,%9}, {%0,%1,%2,%3};\n"
        : "+f"(d[0]), "+f"(d[1]), "+f"(d[2]), "+f"(d[3])
        : "r"(a[0]), "r"(a[1]), "r"(a[2]), "r"(a[3]), "r"(b[0]), "r"(b[1]));
}

// ---------------------------- prep kernels ----------------------------------
// x[b][c][n] fp32 -> xT[b][n][c] fp16
__global__ void xpose_h(const float* __restrict__ x, __half* __restrict__ xT) {
    __shared__ float t[32][33];
    const int b = blockIdx.z;
    const float* xb = x + (size_t)b * 512 * 4096;
    const int n0 = blockIdx.x * 32, c0 = blockIdx.y * 32;
    const int tx = threadIdx.x, ty0 = threadIdx.y;
#pragma unroll
    for (int i = 0; i < 4; i++) {
        int ty = ty0 + i * 8;
        t[ty][tx] = xb[(size_t)(c0 + ty) * 4096 + n0 + tx];
    }
    __syncthreads();
    const size_t ob = (size_t)b * 4096 * 512;
#pragma unroll
    for (int i = 0; i < 4; i++) {
        int ty = ty0 + i * 8;
        xT[ob + (size_t)(n0 + ty) * 512 + c0 + tx] = __float2half_rn(t[tx][ty]);
    }
}

// W[Mvalid][K] fp32 -> fp16 [Mout][K] zero-padded; bias padded
__global__ void conv_pad_w(const float* __restrict__ W, const float* __restrict__ b,
                           __half* __restrict__ Wh, float* __restrict__ bp,
                           int Mout, int Mvalid, int Kd) {
    int idx = blockIdx.x * blockDim.x + threadIdx.x;
    if (idx < Mout * Kd) {
        int m = idx / Kd;
        Wh[idx] = __float2half_rn((m < Mvalid) ? W[idx] : 0.0f);
    }
    if (idx < Mout) bp[idx] = (idx < Mvalid) ? b[idx] : 0.0f;
}

// ------------------------------- GEMM ---------------------------------------
// EPI: 0 = fp32 store ; 1 = +bias[col] -> fp16 ; 2 = +bias[row] -> fp16 ; 3 = sigmoid -> fp16
template <int EPI>
__global__ __launch_bounds__(128, 2)
void gemm_h(const __half* __restrict__ Ag, size_t sA,
            const __half* __restrict__ Bg, size_t sB,
            void* Dg, size_t sD,
            const float* __restrict__ bias,
            int Ntot, int K) {
    extern __shared__ __align__(1024) char smem[];
    const uint32_t sb = (uint32_t)__cvta_generic_to_shared(smem);

    const __half* A = Ag + (size_t)blockIdx.z * sA;
    const __half* B = Bg + (size_t)blockIdx.z * sB;
    const int m0 = blockIdx.y * BM;
    const int n0 = blockIdx.x * BN;
    const int tid  = threadIdx.x;
    const int lane = tid & 31;
    const int w    = tid >> 5;
    const int wm   = (w & 1) * 64;          // 2 warps over M
    const int wn   = (w >> 1) * 64;         // 2 warps over N
    const int g    = lane >> 2;
    const int tg   = lane & 3;

    const int T = K / BKH;

    auto load_stage = [&](int t, int s) {
        const uint32_t st = sb + (uint32_t)(s * STAGE);
        const int kc = t * BKH;
#pragma unroll
        for (int i = 0; i < 16; i++) {
            int idx = tid + i * 128;            // 0..2047
            int isB = idx >> 10;                // first 1024 A, then B
            int r   = (idx & 1023) >> 3;        // row 0..127
            int c   = idx & 7;                  // 16B chunk
            uint32_t dst = st + (uint32_t)(isB * 16384 + r * 128 + ((c ^ (r & 7)) << 4));
            const __half* gp = (isB ? B + (size_t)(n0 + r) * K
                                    : A + (size_t)(m0 + r) * K) + kc + c * 8;
            asm volatile("cp.async.cg.shared.global [%0], [%1], 16;" :: "r"(dst), "l"(gp) : "memory");
        }
        asm volatile("cp.async.commit_group;" ::: "memory");
    };

    float acc[4][8][4];
#pragma unroll
    for (int i = 0; i < 4; i++)
#pragma unroll
        for (int j = 0; j < 8; j++)
#pragma unroll
            for (int r = 0; r < 4; r++) acc[i][j][r] = 0.0f;

    load_stage(0, 0);
    load_stage(1, 1);

    // ldmatrix lane addressing
    const int rowA = wm + (lane & 15);                        // + im*16
    const int hiA  = lane >> 4;                               // k8 chunk +0/+1
    const int rowB = wn + ((lane >> 4) << 3) + (lane & 7);    // + jn*16
    const int hiB  = (lane >> 3) & 1;

    for (int t = 0; t < T; t++) {
        asm volatile("cp.async.wait_group 1;" ::: "memory");
        __syncthreads();
        if (t + 2 < T) load_stage(t + 2, (t + 2) % NSTAGE);

        const uint32_t st  = sb + (uint32_t)((t % NSTAGE) * STAGE);
        const uint32_t stB = st + 16384;
#pragma unroll
        for (int ks = 0; ks < 4; ks++) {
            uint32_t af[4][4], bf[8][2];
#pragma unroll
            for (int im = 0; im < 4; im++) {
                const int r = rowA + im * 16;
                const int c = (ks * 2 + hiA) ^ (r & 7);
                ldsm_x4(af[im][0], af[im][1], af[im][2], af[im][3],
                        st + (uint32_t)(r * 128 + (c << 4)));
            }
#pragma unroll
            for (int jn = 0; jn < 4; jn++) {
                const int r = rowB + jn * 16;
                const int c = (ks * 2 + hiB) ^ (r & 7);
                ldsm_x4(bf[2*jn][0], bf[2*jn][1], bf[2*jn+1][0], bf[2*jn+1][1],
                        stB + (uint32_t)(r * 128 + (c << 4)));
            }
#pragma unroll
            for (int im = 0; im < 4; im++)
#pragma unroll
                for (int in = 0; in < 8; in++)
                    mma_fp16(acc[im][in], af[im], bf[in]);
        }
    }

    // ------------------------------ epilogue ---------------------------------
#pragma unroll
    for (int im = 0; im < 4; im++) {
        const int r0 = m0 + wm + im * 16 + g;
#pragma unroll
        for (int in = 0; in < 8; in++) {
            const int c = n0 + wn + in * 8 + 2 * tg;
#pragma unroll
            for (int h = 0; h < 2; h++) {
                const int r = r0 + h * 8;
                float vx = acc[im][in][2 * h];
                float vy = acc[im][in][2 * h + 1];
                if (EPI == 1) { vx += bias[c]; vy += bias[c + 1]; }
                if (EPI == 2) { float bb = bias[r]; vx += bb; vy += bb; }
                if (EPI == 3) {
                    vx = __fdividef(1.0f, 1.0f + __expf(-vx));
                    vy = __fdividef(1.0f, 1.0f + __expf(-vy));
                }
                if (EPI == 0) {
                    float* D = (float*)Dg + (size_t)blockIdx.z * sD + (size_t)r * Ntot + c;
                    *reinterpret_cast<float2*>(D) = make_float2(vx, vy);
                } else {
                    __half* D = (__half*)Dg + (size_t)blockIdx.z * sD + (size_t)r * Ntot + c;
                    *reinterpret_cast<__half2*>(D) = __floats2half2_rn(vx, vy);
                }
            }
        }
    }
}

// ------------------------------- launch -------------------------------------
extern "C" void kernel_launch(void* const* d_in, const int* in_sizes, int n_in,
                              void* d_out, int out_size) {
    (void)in_sizes; (void)n_in; (void)out_size;
    const float* x  = (const float*)d_in[0];
    const float* Wq = (const float*)d_in[1];
    const float* bq = (const float*)d_in[2];
    const float* Wk = (const float*)d_in[3];
    const float* bk = (const float*)d_in[4];
    const float* Wv = (const float*)d_in[5];
    const float* bv = (const float*)d_in[6];
    float* out = (float*)d_out;

    __half *xT,*Wqh,*Wkh,*Wvh,*q,*k,*v,*a;
    float *bqp,*bkp,*bvp;
    cudaGetSymbolAddress((void**)&xT,  g_xT);
    cudaGetSymbolAddress((void**)&Wqh, g_Wq);
    cudaGetSymbolAddress((void**)&Wkh, g_Wk);
    cudaGetSymbolAddress((void**)&Wvh, g_Wv);
    cudaGetSymbolAddress((void**)&bqp, g_bq);
    cudaGetSymbolAddress((void**)&bkp, g_bk);
    cudaGetSymbolAddress((void**)&bvp, g_bv);
    cudaGetSymbolAddress((void**)&q,   g_q);
    cudaGetSymbolAddress((void**)&k,   g_k);
    cudaGetSymbolAddress((void**)&v,   g_v);
    cudaGetSymbolAddress((void**)&a,   g_a);

    cudaFuncSetAttribute(gemm_h<0>, cudaFuncAttributeMaxDynamicSharedMemorySize, SMEM_TOTAL);
    cudaFuncSetAttribute(gemm_h<1>, cudaFuncAttributeMaxDynamicSharedMemorySize, SMEM_TOTAL);
    cudaFuncSetAttribute(gemm_h<2>, cudaFuncAttributeMaxDynamicSharedMemorySize, SMEM_TOTAL);
    cudaFuncSetAttribute(gemm_h<3>, cudaFuncAttributeMaxDynamicSharedMemorySize, SMEM_TOTAL);

    xpose_h<<<dim3(128, 16, 4), dim3(32, 8)>>>(x, xT);
    conv_pad_w<<<(1024*512 + 255)/256, 256>>>(Wq, bq, Wqh, bqp, 1024, 1000, 512);
    conv_pad_w<<<(1024*512 + 255)/256, 256>>>(Wk, bk, Wkh, bkp, 1024, 1000, 512);
    conv_pad_w<<<(512*512  + 255)/256, 256>>>(Wv, bv, Wvh, bvp,  512,  512, 512);

    const size_t sXT = (size_t)4096 * 512;
    const size_t sQT = (size_t)4096 * 1024;
    const size_t sV  = (size_t)512 * 4096;
    const size_t sAL = (size_t)4096 * 4096;
    const size_t sO  = (size_t)512 * 4096;

    // qT[n,o] = xT·Wq (M=4096,N=1024,K=512) + col bias
    gemm_h<1><<<dim3(8, 32, 4), 128, SMEM_TOTAL>>>(xT, sXT, Wqh, 0, q, sQT, bqp, 1024, 512);
    // kT[m,o] = xT·Wk
    gemm_h<1><<<dim3(8, 32, 4), 128, SMEM_TOTAL>>>(xT, sXT, Wkh, 0, k, sQT, bkp, 1024, 512);
    // v[c,n] = Wv·xT (M=512,N=4096,K=512) + row bias
    gemm_h<2><<<dim3(32, 4, 4), 128, SMEM_TOTAL>>>(Wvh, 0, xT, sXT, v, sV, bvp, 4096, 512);
    // aT[m,n] = sigmoid(kT·qT) (M=N=4096,K=1024)
    gemm_h<3><<<dim3(32, 32, 4), 128, SMEM_TOTAL>>>(k, sQT, q, sQT, a, sAL, nullptr, 4096, 1024);
    // out[c,m] = v·aT (M=512,N=4096,K=4096) fp32
    gemm_h<0><<<dim3(32, 4, 4), 128, SMEM_TOTAL>>>(v, sV, a, sAL, out, sO, nullptr, 4096, 4096);
}